// round 6
// baseline (speedup 1.0000x reference)
#include <cuda_runtime.h>
#include <cuda_bf16.h>
#include <cstdint>

#define Bb 4
#define Tt 2048
#define Cc 1024
#define Hh 16
#define HD 64
#define MR (Bb*Tt)      // 8192 rows

// ---------------------------------------------------------------------------
// device scratch (allocation-free rule)
// ---------------------------------------------------------------------------
__device__ __nv_bfloat16 g_Qhi[Bb*Hh*Tt*HD];
__device__ __nv_bfloat16 g_Qlo[Bb*Hh*Tt*HD];
__device__ __nv_bfloat16 g_Khi[Bb*Hh*Tt*HD];
__device__ __nv_bfloat16 g_Klo[Bb*Hh*Tt*HD];
__device__ __nv_bfloat16 g_Vhi[Bb*Hh*Tt*HD];
__device__ __nv_bfloat16 g_Vlo[Bb*Hh*Tt*HD];
__device__ __nv_bfloat16 g_Vthi[Bb*Hh*Tt*HD];   // [bh][d][kv]
__device__ __nv_bfloat16 g_Vtlo[Bb*Hh*Tt*HD];
__device__ __nv_bfloat16 g_Xhi[MR*Cc];
__device__ __nv_bfloat16 g_Xlo[MR*Cc];
__device__ __nv_bfloat16 g_WAhi[3*Cc*Cc];
__device__ __nv_bfloat16 g_WAlo[3*Cc*Cc];
__device__ __nv_bfloat16 g_WPhi[Cc*Cc];
__device__ __nv_bfloat16 g_WPlo[Cc*Cc];
__device__ __nv_bfloat16 g_Yhi[MR*Cc];
__device__ __nv_bfloat16 g_Ylo[MR*Cc];

// ---------------------------------------------------------------------------
// helpers (base sm_10x-legal PTX only: cp.async / ldmatrix / mma.sync)
// ---------------------------------------------------------------------------
__device__ __forceinline__ uint32_t smem_u32(const void* p) {
    uint32_t a;
    asm("{ .reg .u64 t; cvta.to.shared.u64 t, %1; cvt.u32.u64 %0, t; }" : "=r"(a) : "l"(p));
    return a;
}

__device__ __forceinline__ void cp_async16(uint32_t s, const void* g) {
    asm volatile("cp.async.cg.shared.global [%0], [%1], 16;" :: "r"(s), "l"(g));
}
__device__ __forceinline__ void cp_commit() {
    asm volatile("cp.async.commit_group;" ::: "memory");
}

#define LDSM_X4(r, addr) \
    asm volatile("ldmatrix.sync.aligned.m8n8.x4.shared.b16 {%0,%1,%2,%3}, [%4];" \
        : "=r"((r)[0]), "=r"((r)[1]), "=r"((r)[2]), "=r"((r)[3]) : "r"(addr))

#define MMA16816(c, a, b0v, b1v) \
    asm volatile("mma.sync.aligned.m16n8k16.row.col.f32.bf16.bf16.f32 " \
        "{%0,%1,%2,%3}, {%4,%5,%6,%7}, {%8,%9}, {%0,%1,%2,%3};" \
        : "+f"((c)[0]), "+f"((c)[1]), "+f"((c)[2]), "+f"((c)[3]) \
        : "r"((a)[0]), "r"((a)[1]), "r"((a)[2]), "r"((a)[3]), "r"(b0v), "r"(b1v))

// ---------------------------------------------------------------------------
// prep kernels
// ---------------------------------------------------------------------------
__global__ void convert_x_kernel(const float4* __restrict__ x, int n4) {
    __nv_bfloat162* hi2 = (__nv_bfloat162*)g_Xhi;
    __nv_bfloat162* lo2 = (__nv_bfloat162*)g_Xlo;
    for (int i = blockIdx.x * blockDim.x + threadIdx.x; i < n4; i += gridDim.x * blockDim.x) {
        float4 v = x[i];
        __nv_bfloat16 h0 = __float2bfloat16(v.x), h1 = __float2bfloat16(v.y);
        __nv_bfloat16 h2 = __float2bfloat16(v.z), h3 = __float2bfloat16(v.w);
        __nv_bfloat162 a, b, c, d;
        a.x = h0; a.y = h1; b.x = h2; b.y = h3;
        c.x = __float2bfloat16(v.x - __bfloat162float(h0));
        c.y = __float2bfloat16(v.y - __bfloat162float(h1));
        d.x = __float2bfloat16(v.z - __bfloat162float(h2));
        d.y = __float2bfloat16(v.w - __bfloat162float(h3));
        hi2[i * 2] = a; hi2[i * 2 + 1] = b;
        lo2[i * 2] = c; lo2[i * 2 + 1] = d;
    }
}

// src [K,N] fp32 -> dst [N,K] bf16 hi/lo
__global__ void transconv_kernel(const float* __restrict__ src, __nv_bfloat16* __restrict__ dhi,
                                 __nv_bfloat16* __restrict__ dlo, int K, int N) {
    __shared__ float sm[32][33];
    int n0 = blockIdx.x * 32, k0 = blockIdx.y * 32;
    int tx = threadIdx.x, ty = threadIdx.y;   // 32 x 8
#pragma unroll
    for (int i = 0; i < 32; i += 8)
        sm[ty + i][tx] = src[(size_t)(k0 + ty + i) * N + n0 + tx];
    __syncthreads();
#pragma unroll
    for (int i = 0; i < 32; i += 8) {
        float v = sm[tx][ty + i];
        __nv_bfloat16 h = __float2bfloat16(v);
        size_t o = (size_t)(n0 + ty + i) * K + k0 + tx;
        dhi[o] = h;
        dlo[o] = __float2bfloat16(v - __bfloat162float(h));
    }
}

// V [bh][kv][d] bf16 -> Vt [bh][d][kv] bf16 (hi and lo)
__global__ void vtrans_kernel() {
    __shared__ __nv_bfloat16 th[32][33], tl[32][33];
    int kv0 = blockIdx.x * 32, d0 = blockIdx.y * 32, bh = blockIdx.z;
    int tx = threadIdx.x, ty = threadIdx.y;   // 32 x 8
    const __nv_bfloat16* sh = g_Vhi + (size_t)bh * Tt * HD;
    const __nv_bfloat16* sl = g_Vlo + (size_t)bh * Tt * HD;
    __nv_bfloat16* dh = g_Vthi + (size_t)bh * HD * Tt;
    __nv_bfloat16* dl = g_Vtlo + (size_t)bh * HD * Tt;
#pragma unroll
    for (int i = 0; i < 32; i += 8) {
        th[ty + i][tx] = sh[(size_t)(kv0 + ty + i) * HD + d0 + tx];
        tl[ty + i][tx] = sl[(size_t)(kv0 + ty + i) * HD + d0 + tx];
    }
    __syncthreads();
#pragma unroll
    for (int i = 0; i < 32; i += 8) {
        dh[(size_t)(d0 + ty + i) * Tt + kv0 + tx] = th[tx][ty + i];
        dl[(size_t)(d0 + ty + i) * Tt + kv0 + tx] = tl[tx][ty + i];
    }
}

// ---------------------------------------------------------------------------
// HMMA bf16 (hi/lo split) GEMM: CTA tile 128x128, K chunks of 32, cp.async x2buf
// MMAs issued in 3 term-passes (chain distance 16) to hide HMMA latency.
// MODE 0: emit Q(0.125x)/K/V as bf16 hi/lo into [bh][t][d] arrays.
// MODE 1: row-major fp32 out [MR,Cc].
// ---------------------------------------------------------------------------
#define BK 32
#define PAD 40
#define MAT_BYTES (128*PAD*2)        // 10240
#define BUFB (4*MAT_BYTES)           // 40960
#define GSMEM (2*BUFB)               // 81920

__device__ __forceinline__ void issue_chunk(
    uint32_t sbase,
    const __nv_bfloat16* __restrict__ Ahi, const __nv_bfloat16* __restrict__ Alo,
    const __nv_bfloat16* __restrict__ Bhi, const __nv_bfloat16* __restrict__ Blo,
    int m0, int n0, int kc, int tid)
{
#pragma unroll
    for (int it = 0; it < 2; it++) {
        int idx = it * 256 + tid;
        int row = idx >> 2, seg = idx & 3;
        uint32_t soff = (uint32_t)(row * PAD + seg * 8) * 2;
        size_t ga = (size_t)(m0 + row) * Cc + kc + seg * 8;
        size_t gb = (size_t)(n0 + row) * Cc + kc + seg * 8;
        cp_async16(sbase + soff,                 Ahi + ga);
        cp_async16(sbase + MAT_BYTES + soff,     Alo + ga);
        cp_async16(sbase + 2*MAT_BYTES + soff,   Bhi + gb);
        cp_async16(sbase + 3*MAT_BYTES + soff,   Blo + gb);
    }
    cp_commit();
}

template <int MODE>
__global__ __launch_bounds__(256, 1)
void tc_gemm(const __nv_bfloat16* __restrict__ Ahi, const __nv_bfloat16* __restrict__ Alo,
             const __nv_bfloat16* __restrict__ Bhi, const __nv_bfloat16* __restrict__ Blo,
             const float* __restrict__ bias, float* __restrict__ out) {
    extern __shared__ char smx[];
    uint32_t sb = smem_u32(smx);
    int tid = threadIdx.x;
    int lane = tid & 31, warp = tid >> 5;
    int wm = warp & 3;
    int wn = warp >> 2;
    int m0 = blockIdx.y * 128, n0 = blockIdx.x * 128;

    float acc[2][8][4] = {};

    issue_chunk(sb, Ahi, Alo, Bhi, Blo, m0, n0, 0, tid);

    const int NCH = Cc / BK;   // 32
    int arow = wm * 32 + (lane & 15);
    int acol_base = (lane >> 4) * 8;
    int brow = wn * 64 + (lane >> 4) * 8 + (lane & 7);
    int bcol_base = ((lane >> 3) & 1) * 8;

    for (int i = 0; i < NCH; i++) {
        if (i + 1 < NCH) {
            issue_chunk(sb + ((i + 1) & 1) * BUFB, Ahi, Alo, Bhi, Blo, m0, n0, (i + 1) * BK, tid);
            asm volatile("cp.async.wait_group 1;" ::: "memory");
        } else {
            asm volatile("cp.async.wait_group 0;" ::: "memory");
        }
        __syncthreads();
        uint32_t buf = sb + (i & 1) * BUFB;

#pragma unroll
        for (int ks = 0; ks < 2; ks++) {
            uint32_t ah[2][4], al[2][4], bhf[4][4], blf[4][4];
            int acol = ks * 16 + acol_base;
#pragma unroll
            for (int mt = 0; mt < 2; mt++) {
                uint32_t addr = buf + (uint32_t)((arow + mt * 16) * PAD + acol) * 2;
                LDSM_X4(ah[mt], addr);
                LDSM_X4(al[mt], addr + MAT_BYTES);
            }
            int bcol = ks * 16 + bcol_base;
#pragma unroll
            for (int np = 0; np < 4; np++) {
                uint32_t addr = buf + 2 * MAT_BYTES +
                                (uint32_t)((brow + np * 16) * PAD + bcol) * 2;
                LDSM_X4(bhf[np], addr);
                LDSM_X4(blf[np], addr + MAT_BYTES);
            }
            // term pass 1: hi*hi (16 independent MMAs)
#pragma unroll
            for (int np = 0; np < 4; np++)
#pragma unroll
                for (int mt = 0; mt < 2; mt++)
#pragma unroll
                    for (int half = 0; half < 2; half++)
                        MMA16816(acc[mt][np * 2 + half], ah[mt],
                                 bhf[np][half * 2], bhf[np][half * 2 + 1]);
            // term pass 2: hi*lo
#pragma unroll
            for (int np = 0; np < 4; np++)
#pragma unroll
                for (int mt = 0; mt < 2; mt++)
#pragma unroll
                    for (int half = 0; half < 2; half++)
                        MMA16816(acc[mt][np * 2 + half], ah[mt],
                                 blf[np][half * 2], blf[np][half * 2 + 1]);
            // term pass 3: lo*hi
#pragma unroll
            for (int np = 0; np < 4; np++)
#pragma unroll
                for (int mt = 0; mt < 2; mt++)
#pragma unroll
                    for (int half = 0; half < 2; half++)
                        MMA16816(acc[mt][np * 2 + half], al[mt],
                                 bhf[np][half * 2], bhf[np][half * 2 + 1]);
        }
        __syncthreads();
    }

    int mrow = m0 + wm * 32 + (lane >> 2);
#pragma unroll
    for (int mt = 0; mt < 2; mt++) {
#pragma unroll
        for (int nt = 0; nt < 8; nt++) {
            int n = n0 + wn * 64 + nt * 8 + (lane & 3) * 2;
            float bx = bias[n], by = bias[n + 1];
            float2 v0 = make_float2(acc[mt][nt][0] + bx, acc[mt][nt][1] + by);
            float2 v1 = make_float2(acc[mt][nt][2] + bx, acc[mt][nt][3] + by);
            int m_a = mrow + mt * 16;
            int m_b = m_a + 8;
            if (MODE == 0) {
                int sec = n >> 10;
                int c2 = n & (Cc - 1);
                int h = c2 >> 6, d = c2 & 63;
                __nv_bfloat16 *dh, *dl;
                float scale;
                if (sec == 0)      { dh = g_Qhi; dl = g_Qlo; scale = 0.125f; }
                else if (sec == 1) { dh = g_Khi; dl = g_Klo; scale = 1.0f; }
                else               { dh = g_Vhi; dl = g_Vlo; scale = 1.0f; }
                v0.x *= scale; v0.y *= scale; v1.x *= scale; v1.y *= scale;
                int ba = m_a >> 11, ta = m_a & (Tt - 1);
                int bb2 = m_b >> 11, tb = m_b & (Tt - 1);
                size_t o0 = (((size_t)(ba * Hh + h)) * Tt + ta) * HD + d;
                size_t o1 = (((size_t)(bb2 * Hh + h)) * Tt + tb) * HD + d;
                __nv_bfloat162 hi = __floats2bfloat162_rn(v0.x, v0.y);
                __nv_bfloat162 lo = __floats2bfloat162_rn(
                    v0.x - __bfloat162float(hi.x), v0.y - __bfloat162float(hi.y));
                *(__nv_bfloat162*)&dh[o0] = hi;
                *(__nv_bfloat162*)&dl[o0] = lo;
                hi = __floats2bfloat162_rn(v1.x, v1.y);
                lo = __floats2bfloat162_rn(
                    v1.x - __bfloat162float(hi.x), v1.y - __bfloat162float(hi.y));
                *(__nv_bfloat162*)&dh[o1] = hi;
                *(__nv_bfloat162*)&dl[o1] = lo;
            } else {
                *(float2*)&out[(size_t)m_a * Cc + n] = v0;
                *(float2*)&out[(size_t)m_b * Cc + n] = v1;
            }
        }
    }
}

// ---------------------------------------------------------------------------
// Tensor-core flash attention, bf16 hi/lo split (3-term), Bq=64, Bk=64,
// 128 threads (4 warps x 16 q-rows). Term-pass MMA scheduling.
// ---------------------------------------------------------------------------
#define APAD 72
#define AMAT (64*APAD)               // elems per smem matrix
#define ASMEM (6*AMAT*2)             // 55296 B

__global__ __launch_bounds__(128, 3) void attn_tc() {
    extern __shared__ __nv_bfloat16 sa[];
    __nv_bfloat16* Qh = sa;
    __nv_bfloat16* Ql = sa + AMAT;
    __nv_bfloat16* Kh = sa + 2 * AMAT;
    __nv_bfloat16* Kl = sa + 3 * AMAT;
    __nv_bfloat16* Vh = sa + 4 * AMAT;
    __nv_bfloat16* Vl = sa + 5 * AMAT;
    uint32_t sQh = smem_u32(Qh), sQl = smem_u32(Ql);
    uint32_t sKh = smem_u32(Kh), sKl = smem_u32(Kl);
    uint32_t sVh = smem_u32(Vh), sVl = smem_u32(Vl);

    int tid = threadIdx.x;
    int lane = tid & 31, w = tid >> 5;
    int bh = blockIdx.y;
    int qtile = (gridDim.x - 1) - blockIdx.x;    // heavy tiles first
    int q0 = qtile * 64;

    const __nv_bfloat16* gQh = g_Qhi + (size_t)bh * Tt * HD;
    const __nv_bfloat16* gQl = g_Qlo + (size_t)bh * Tt * HD;
    const __nv_bfloat16* gKh = g_Khi + (size_t)bh * Tt * HD;
    const __nv_bfloat16* gKl = g_Klo + (size_t)bh * Tt * HD;
    const __nv_bfloat16* gVh = g_Vthi + (size_t)bh * HD * Tt;
    const __nv_bfloat16* gVl = g_Vtlo + (size_t)bh * HD * Tt;

#pragma unroll
    for (int it = 0; it < 4; it++) {
        int idx = it * 128 + tid;
        int row = idx >> 3, seg = idx & 7;
        uint32_t so = (uint32_t)(row * APAD + seg * 8) * 2;
        size_t go = (size_t)(q0 + row) * HD + seg * 8;
        cp_async16(sQh + so, gQh + go);
        cp_async16(sQl + so, gQl + go);
    }
    cp_commit();

    float o[8][4] = {};
    float mrow[2] = {-1e30f, -1e30f};
    float lrow[2] = {0.0f, 0.0f};

    int r0 = lane >> 2;
    int qrow_loc = w * 16 + r0;

    for (int kt = 0; kt <= qtile; kt++) {
        int kv0 = kt * 64;
        __syncthreads();
#pragma unroll
        for (int it = 0; it < 4; it++) {
            int idx = it * 128 + tid;
            int row = idx >> 3, seg = idx & 7;
            uint32_t so = (uint32_t)(row * APAD + seg * 8) * 2;
            size_t gk = (size_t)(kv0 + row) * HD + seg * 8;
            size_t gv = (size_t)row * Tt + kv0 + seg * 8;
            cp_async16(sKh + so, gKh + gk);
            cp_async16(sKl + so, gKl + gk);
            cp_async16(sVh + so, gVh + gv);
            cp_async16(sVl + so, gVl + gv);
        }
        cp_commit();
        asm volatile("cp.async.wait_group 0;" ::: "memory");
        __syncthreads();

        // ---- S = Q K^T  (3-term split, term-pass scheduling) ----
        float s[8][4] = {};
#pragma unroll
        for (int ks = 0; ks < 4; ks++) {
            uint32_t aqh[4], aql[4], bkh[4][4], bkl[4][4];
            uint32_t aaddr = (uint32_t)((w * 16 + (lane & 15)) * APAD + ks * 16 + (lane >> 4) * 8) * 2;
            LDSM_X4(aqh, sQh + aaddr);
            LDSM_X4(aql, sQl + aaddr);
#pragma unroll
            for (int ntp = 0; ntp < 4; ntp++) {
                uint32_t baddr = (uint32_t)((ntp * 16 + (lane >> 4) * 8 + (lane & 7)) * APAD +
                                            ks * 16 + ((lane >> 3) & 1) * 8) * 2;
                LDSM_X4(bkh[ntp], sKh + baddr);
                LDSM_X4(bkl[ntp], sKl + baddr);
            }
#pragma unroll
            for (int ntp = 0; ntp < 4; ntp++)
#pragma unroll
                for (int h2 = 0; h2 < 2; h2++)
                    MMA16816(s[ntp * 2 + h2], aqh, bkh[ntp][h2 * 2], bkh[ntp][h2 * 2 + 1]);
#pragma unroll
            for (int ntp = 0; ntp < 4; ntp++)
#pragma unroll
                for (int h2 = 0; h2 < 2; h2++)
                    MMA16816(s[ntp * 2 + h2], aqh, bkl[ntp][h2 * 2], bkl[ntp][h2 * 2 + 1]);
#pragma unroll
            for (int ntp = 0; ntp < 4; ntp++)
#pragma unroll
                for (int h2 = 0; h2 < 2; h2++)
                    MMA16816(s[ntp * 2 + h2], aql, bkh[ntp][h2 * 2], bkh[ntp][h2 * 2 + 1]);
        }

        if (kt == qtile) {
#pragma unroll
            for (int nt = 0; nt < 8; nt++) {
#pragma unroll
                for (int j = 0; j < 4; j++) {
                    int c = nt * 8 + (lane & 3) * 2 + (j & 1);
                    int r = qrow_loc + ((j >> 1) ? 8 : 0);
                    if (c > r) s[nt][j] = -1e30f;
                }
            }
        }

        // ---- online softmax ----
#pragma unroll
        for (int rr = 0; rr < 2; rr++) {
            float rm = -1e30f;
#pragma unroll
            for (int nt = 0; nt < 8; nt++)
                rm = fmaxf(rm, fmaxf(s[nt][rr * 2], s[nt][rr * 2 + 1]));
            rm = fmaxf(rm, __shfl_xor_sync(0xffffffffu, rm, 1));
            rm = fmaxf(rm, __shfl_xor_sync(0xffffffffu, rm, 2));
            float mnew = fmaxf(mrow[rr], rm);
            float alpha = __expf(mrow[rr] - mnew);
            mrow[rr] = mnew;
            float rs = 0.0f;
#pragma unroll
            for (int nt = 0; nt < 8; nt++) {
                s[nt][rr * 2]     = __expf(s[nt][rr * 2] - mnew);
                s[nt][rr * 2 + 1] = __expf(s[nt][rr * 2 + 1] - mnew);
                rs += s[nt][rr * 2] + s[nt][rr * 2 + 1];
            }
            rs += __shfl_xor_sync(0xffffffffu, rs, 1);
            rs += __shfl_xor_sync(0xffffffffu, rs, 2);
            lrow[rr] = lrow[rr] * alpha + rs;
#pragma unroll
            for (int dt = 0; dt < 8; dt++) {
                o[dt][rr * 2]     *= alpha;
                o[dt][rr * 2 + 1] *= alpha;
            }
        }

        // ---- O += P V  (P from regs, 3-term split, term-pass scheduling) ----
#pragma unroll
        for (int ksv = 0; ksv < 4; ksv++) {
            uint32_t pah[4], pal[4];
#pragma unroll
            for (int q = 0; q < 4; q++) {
                int nt = 2 * ksv + (q >> 1);
                int j0 = (q & 1) * 2;
                float x = s[nt][j0], y = s[nt][j0 + 1];
                __nv_bfloat162 hv = __floats2bfloat162_rn(x, y);
                __nv_bfloat162 lv = __floats2bfloat162_rn(
                    x - __bfloat162float(hv.x), y - __bfloat162float(hv.y));
                pah[q] = *(uint32_t*)&hv;
                pal[q] = *(uint32_t*)&lv;
            }
            uint32_t bvh[4][4], bvl[4][4];
#pragma unroll
            for (int dtp = 0; dtp < 4; dtp++) {
                uint32_t baddr = (uint32_t)((dtp * 16 + (lane >> 4) * 8 + (lane & 7)) * APAD +
                                            ksv * 16 + ((lane >> 3) & 1) * 8) * 2;
                LDSM_X4(bvh[dtp], sVh + baddr);
                LDSM_X4(bvl[dtp], sVl + baddr);
            }
#pragma unroll
            for (int dtp = 0; dtp < 4; dtp++)
#pragma unroll
                for (int h2 = 0; h2 < 2; h2++)
                    MMA16816(o[dtp * 2 + h2], pah, bvh[dtp][h2 * 2], bvh[dtp][h2 * 2 + 1]);
#pragma unroll
            for (int dtp = 0; dtp < 4; dtp++)
#pragma unroll
                for (int h2 = 0; h2 < 2; h2++)
                    MMA16816(o[dtp * 2 + h2], pah, bvl[dtp][h2 * 2], bvl[dtp][h2 * 2 + 1]);
#pragma unroll
            for (int dtp = 0; dtp < 4; dtp++)
#pragma unroll
                for (int h2 = 0; h2 < 2; h2++)
                    MMA16816(o[dtp * 2 + h2], pal, bvh[dtp][h2 * 2], bvh[dtp][h2 * 2 + 1]);
        }
    }

    // ---- epilogue: normalize, emit Y as bf16 hi/lo [B,T,C] ----
    float inv0 = 1.0f / lrow[0];
    float inv1 = 1.0f / lrow[1];
    int b = bh >> 4, h = bh & 15;
    int gq0 = q0 + w * 16 + r0;
    int gq1 = gq0 + 8;
#pragma unroll
    for (int dt = 0; dt < 8; dt++) {
        int col = h * HD + dt * 8 + (lane & 3) * 2;
        size_t o0 = (size_t)(b * Tt + gq0) * Cc + col;
        size_t o1 = (size_t)(b * Tt + gq1) * Cc + col;
        float y0 = o[dt][0] * inv0, y1 = o[dt][1] * inv0;
        float y2 = o[dt][2] * inv1, y3 = o[dt][3] * inv1;
        __nv_bfloat162 hv = __floats2bfloat162_rn(y0, y1);
        __nv_bfloat162 lv = __floats2bfloat162_rn(
            y0 - __bfloat162float(hv.x), y1 - __bfloat162float(hv.y));
        *(__nv_bfloat162*)&g_Yhi[o0] = hv;
        *(__nv_bfloat162*)&g_Ylo[o0] = lv;
        hv = __floats2bfloat162_rn(y2, y3);
        lv = __floats2bfloat162_rn(
            y2 - __bfloat162float(hv.x), y3 - __bfloat162float(hv.y));
        *(__nv_bfloat162*)&g_Yhi[o1] = hv;
        *(__nv_bfloat162*)&g_Ylo[o1] = lv;
    }
}

// ---------------------------------------------------------------------------
extern "C" void kernel_launch(void* const* d_in, const int* in_sizes, int n_in,
                              void* d_out, int out_size) {
    const float* x      = (const float*)d_in[0];
    const float* W_attn = (const float*)d_in[1];
    const float* b_attn = (const float*)d_in[2];
    const float* W_proj = (const float*)d_in[3];
    const float* b_proj = (const float*)d_in[4];
    float* out = (float*)d_out;

    __nv_bfloat16 *xhi, *xlo, *wahi, *walo, *wphi, *wplo, *yhi, *ylo;
    cudaGetSymbolAddress((void**)&xhi,  g_Xhi);
    cudaGetSymbolAddress((void**)&xlo,  g_Xlo);
    cudaGetSymbolAddress((void**)&wahi, g_WAhi);
    cudaGetSymbolAddress((void**)&walo, g_WAlo);
    cudaGetSymbolAddress((void**)&wphi, g_WPhi);
    cudaGetSymbolAddress((void**)&wplo, g_WPlo);
    cudaGetSymbolAddress((void**)&yhi,  g_Yhi);
    cudaGetSymbolAddress((void**)&ylo,  g_Ylo);

    cudaFuncSetAttribute(tc_gemm<0>, cudaFuncAttributeMaxDynamicSharedMemorySize, GSMEM);
    cudaFuncSetAttribute(tc_gemm<1>, cudaFuncAttributeMaxDynamicSharedMemorySize, GSMEM);
    cudaFuncSetAttribute(attn_tc, cudaFuncAttributeMaxDynamicSharedMemorySize, ASMEM);

    convert_x_kernel<<<1024, 256>>>((const float4*)x, MR * Cc / 4);
    transconv_kernel<<<dim3(3 * Cc / 32, Cc / 32), dim3(32, 8)>>>(W_attn, wahi, walo, Cc, 3 * Cc);
    transconv_kernel<<<dim3(Cc / 32, Cc / 32), dim3(32, 8)>>>(W_proj, wphi, wplo, Cc, Cc);

    tc_gemm<0><<<dim3(3 * Cc / 128, MR / 128), 256, GSMEM>>>(xhi, xlo, wahi, walo, b_attn, nullptr);

    vtrans_kernel<<<dim3(Tt / 32, HD / 32, Bb * Hh), dim3(32, 8)>>>();

    attn_tc<<<dim3(Tt / 64, Bb * Hh), 128, ASMEM>>>();

    tc_gemm<1><<<dim3(Cc / 128, MR / 128), 256, GSMEM>>>(yhi, ylo, wphi, wplo, b_proj, out);
}

// round 7
// speedup vs baseline: 1.0879x; 1.0879x over previous
#include <cuda_runtime.h>
#include <cuda_bf16.h>
#include <cstdint>

#define Bb 4
#define Tt 2048
#define Cc 1024
#define Hh 16
#define HD 64
#define MR (Bb*Tt)      // 8192 rows

// ---------------------------------------------------------------------------
// device scratch (allocation-free rule)
// ---------------------------------------------------------------------------
__device__ __nv_bfloat16 g_Qhi[Bb*Hh*Tt*HD];
__device__ __nv_bfloat16 g_Qlo[Bb*Hh*Tt*HD];
__device__ __nv_bfloat16 g_Khi[Bb*Hh*Tt*HD];
__device__ __nv_bfloat16 g_Klo[Bb*Hh*Tt*HD];
__device__ __nv_bfloat16 g_Vhi[Bb*Hh*Tt*HD];
__device__ __nv_bfloat16 g_Vlo[Bb*Hh*Tt*HD];
__device__ __nv_bfloat16 g_Vthi[Bb*Hh*Tt*HD];   // [bh][d][kv]
__device__ __nv_bfloat16 g_Vtlo[Bb*Hh*Tt*HD];
__device__ __nv_bfloat16 g_Xhi[MR*Cc];
__device__ __nv_bfloat16 g_Xlo[MR*Cc];
__device__ __nv_bfloat16 g_WAhi[3*Cc*Cc];
__device__ __nv_bfloat16 g_WAlo[3*Cc*Cc];
__device__ __nv_bfloat16 g_WPhi[Cc*Cc];
__device__ __nv_bfloat16 g_WPlo[Cc*Cc];
__device__ __nv_bfloat16 g_Yhi[MR*Cc];
__device__ __nv_bfloat16 g_Ylo[MR*Cc];

// ---------------------------------------------------------------------------
// helpers (base sm_10x-legal PTX only: cp.async / ldmatrix / mma.sync)
// ---------------------------------------------------------------------------
__device__ __forceinline__ uint32_t smem_u32(const void* p) {
    uint32_t a;
    asm("{ .reg .u64 t; cvta.to.shared.u64 t, %1; cvt.u32.u64 %0, t; }" : "=r"(a) : "l"(p));
    return a;
}

__device__ __forceinline__ void cp_async16(uint32_t s, const void* g) {
    asm volatile("cp.async.cg.shared.global [%0], [%1], 16;" :: "r"(s), "l"(g));
}
__device__ __forceinline__ void cp_commit() {
    asm volatile("cp.async.commit_group;" ::: "memory");
}

#define LDSM_X4(r, addr) \
    asm volatile("ldmatrix.sync.aligned.m8n8.x4.shared.b16 {%0,%1,%2,%3}, [%4];" \
        : "=r"((r)[0]), "=r"((r)[1]), "=r"((r)[2]), "=r"((r)[3]) : "r"(addr))

#define MMA16816(c, a, b0v, b1v) \
    asm volatile("mma.sync.aligned.m16n8k16.row.col.f32.bf16.bf16.f32 " \
        "{%0,%1,%2,%3}, {%4,%5,%6,%7}, {%8,%9}, {%0,%1,%2,%3};" \
        : "+f"((c)[0]), "+f"((c)[1]), "+f"((c)[2]), "+f"((c)[3]) \
        : "r"((a)[0]), "r"((a)[1]), "r"((a)[2]), "r"((a)[3]), "r"(b0v), "r"(b1v))

// ---------------------------------------------------------------------------
// prep kernels
// ---------------------------------------------------------------------------
__global__ void convert_x_kernel(const float4* __restrict__ x, int n4) {
    __nv_bfloat162* hi2 = (__nv_bfloat162*)g_Xhi;
    __nv_bfloat162* lo2 = (__nv_bfloat162*)g_Xlo;
    for (int i = blockIdx.x * blockDim.x + threadIdx.x; i < n4; i += gridDim.x * blockDim.x) {
        float4 v = x[i];
        __nv_bfloat16 h0 = __float2bfloat16(v.x), h1 = __float2bfloat16(v.y);
        __nv_bfloat16 h2 = __float2bfloat16(v.z), h3 = __float2bfloat16(v.w);
        __nv_bfloat162 a, b, c, d;
        a.x = h0; a.y = h1; b.x = h2; b.y = h3;
        c.x = __float2bfloat16(v.x - __bfloat162float(h0));
        c.y = __float2bfloat16(v.y - __bfloat162float(h1));
        d.x = __float2bfloat16(v.z - __bfloat162float(h2));
        d.y = __float2bfloat16(v.w - __bfloat162float(h3));
        hi2[i * 2] = a; hi2[i * 2 + 1] = b;
        lo2[i * 2] = c; lo2[i * 2 + 1] = d;
    }
}

// src [K,N] fp32 -> dst [N,K] bf16 hi/lo
__global__ void transconv_kernel(const float* __restrict__ src, __nv_bfloat16* __restrict__ dhi,
                                 __nv_bfloat16* __restrict__ dlo, int K, int N) {
    __shared__ float sm[32][33];
    int n0 = blockIdx.x * 32, k0 = blockIdx.y * 32;
    int tx = threadIdx.x, ty = threadIdx.y;   // 32 x 8
#pragma unroll
    for (int i = 0; i < 32; i += 8)
        sm[ty + i][tx] = src[(size_t)(k0 + ty + i) * N + n0 + tx];
    __syncthreads();
#pragma unroll
    for (int i = 0; i < 32; i += 8) {
        float v = sm[tx][ty + i];
        __nv_bfloat16 h = __float2bfloat16(v);
        size_t o = (size_t)(n0 + ty + i) * K + k0 + tx;
        dhi[o] = h;
        dlo[o] = __float2bfloat16(v - __bfloat162float(h));
    }
}

// V [bh][kv][d] bf16 -> Vt [bh][d][kv] bf16 (hi and lo)
__global__ void vtrans_kernel() {
    __shared__ __nv_bfloat16 th[32][33], tl[32][33];
    int kv0 = blockIdx.x * 32, d0 = blockIdx.y * 32, bh = blockIdx.z;
    int tx = threadIdx.x, ty = threadIdx.y;   // 32 x 8
    const __nv_bfloat16* sh = g_Vhi + (size_t)bh * Tt * HD;
    const __nv_bfloat16* sl = g_Vlo + (size_t)bh * Tt * HD;
    __nv_bfloat16* dh = g_Vthi + (size_t)bh * HD * Tt;
    __nv_bfloat16* dl = g_Vtlo + (size_t)bh * HD * Tt;
#pragma unroll
    for (int i = 0; i < 32; i += 8) {
        th[ty + i][tx] = sh[(size_t)(kv0 + ty + i) * HD + d0 + tx];
        tl[ty + i][tx] = sl[(size_t)(kv0 + ty + i) * HD + d0 + tx];
    }
    __syncthreads();
#pragma unroll
    for (int i = 0; i < 32; i += 8) {
        dh[(size_t)(d0 + ty + i) * Tt + kv0 + tx] = th[tx][ty + i];
        dl[(size_t)(d0 + ty + i) * Tt + kv0 + tx] = tl[tx][ty + i];
    }
}

// ---------------------------------------------------------------------------
// HMMA bf16 (hi/lo split) GEMM: CTA tile 128x64, K chunks of 32, cp.async x2buf
// 8 warps of 32x32; low regs -> 2 CTAs/SM (16 warps) to hide latency/syncs.
// MODE 0: emit Q(0.125x)/K/V as bf16 hi/lo into [bh][t][d] arrays.
// MODE 1: row-major fp32 out [MR,Cc].
// ---------------------------------------------------------------------------
#define BK 32
#define PAD 40
#define AMATB (128*PAD*2)            // 10240 (A hi or lo)
#define BMATB (64*PAD*2)             // 5120  (B hi or lo)
#define B_OFF (2*AMATB)              // 20480
#define BUFB (2*AMATB + 2*BMATB)     // 30720
#define GSMEM (2*BUFB)               // 61440

__device__ __forceinline__ void issue_chunk(
    uint32_t sbase,
    const __nv_bfloat16* __restrict__ Ahi, const __nv_bfloat16* __restrict__ Alo,
    const __nv_bfloat16* __restrict__ Bhi, const __nv_bfloat16* __restrict__ Blo,
    int m0, int n0, int kc, int tid)
{
    // A: 128 rows x 32 cols (4 segs of 8), hi+lo
#pragma unroll
    for (int it = 0; it < 2; it++) {
        int idx = it * 256 + tid;            // 0..511
        int row = idx >> 2, seg = idx & 3;
        uint32_t soff = (uint32_t)(row * PAD + seg * 8) * 2;
        size_t ga = (size_t)(m0 + row) * Cc + kc + seg * 8;
        cp_async16(sbase + soff,         Ahi + ga);
        cp_async16(sbase + AMATB + soff, Alo + ga);
    }
    // B: 64 rows x 32 cols, hi+lo
    {
        int row = tid >> 2, seg = tid & 3;
        uint32_t soff = (uint32_t)(row * PAD + seg * 8) * 2;
        size_t gb = (size_t)(n0 + row) * Cc + kc + seg * 8;
        cp_async16(sbase + B_OFF + soff,         Bhi + gb);
        cp_async16(sbase + B_OFF + BMATB + soff, Blo + gb);
    }
    cp_commit();
}

template <int MODE>
__global__ __launch_bounds__(256, 2)
void tc_gemm(const __nv_bfloat16* __restrict__ Ahi, const __nv_bfloat16* __restrict__ Alo,
             const __nv_bfloat16* __restrict__ Bhi, const __nv_bfloat16* __restrict__ Blo,
             const float* __restrict__ bias, float* __restrict__ out) {
    extern __shared__ char smx[];
    uint32_t sb = smem_u32(smx);
    int tid = threadIdx.x;
    int lane = tid & 31, warp = tid >> 5;
    int wm = warp & 3;          // 4 m-warps (32 rows each)
    int wn = warp >> 2;         // 2 n-warps (32 cols each)
    int m0 = blockIdx.y * 128, n0 = blockIdx.x * 64;

    float acc[2][4][4] = {};    // [mt][np*2+half][frag]

    issue_chunk(sb, Ahi, Alo, Bhi, Blo, m0, n0, 0, tid);

    const int NCH = Cc / BK;   // 32
    int arow = wm * 32 + (lane & 15);
    int acol_base = (lane >> 4) * 8;
    int brow = wn * 32 + (lane >> 4) * 8 + (lane & 7);
    int bcol_base = ((lane >> 3) & 1) * 8;

    for (int i = 0; i < NCH; i++) {
        if (i + 1 < NCH) {
            issue_chunk(sb + ((i + 1) & 1) * BUFB, Ahi, Alo, Bhi, Blo, m0, n0, (i + 1) * BK, tid);
            asm volatile("cp.async.wait_group 1;" ::: "memory");
        } else {
            asm volatile("cp.async.wait_group 0;" ::: "memory");
        }
        __syncthreads();
        uint32_t buf = sb + (i & 1) * BUFB;

#pragma unroll
        for (int ks = 0; ks < 2; ks++) {
            uint32_t ah[2][4], al[2][4], bhf[2][4], blf[2][4];
            int acol = ks * 16 + acol_base;
#pragma unroll
            for (int mt = 0; mt < 2; mt++) {
                uint32_t addr = buf + (uint32_t)((arow + mt * 16) * PAD + acol) * 2;
                LDSM_X4(ah[mt], addr);
                LDSM_X4(al[mt], addr + AMATB);
            }
            int bcol = ks * 16 + bcol_base;
#pragma unroll
            for (int np = 0; np < 2; np++) {
                uint32_t addr = buf + B_OFF +
                                (uint32_t)((brow + np * 16) * PAD + bcol) * 2;
                LDSM_X4(bhf[np], addr);
                LDSM_X4(blf[np], addr + BMATB);
            }
            // three term passes, 8 independent MMAs each
#pragma unroll
            for (int np = 0; np < 2; np++)
#pragma unroll
                for (int mt = 0; mt < 2; mt++)
#pragma unroll
                    for (int half = 0; half < 2; half++)
                        MMA16816(acc[mt][np * 2 + half], ah[mt],
                                 bhf[np][half * 2], bhf[np][half * 2 + 1]);
#pragma unroll
            for (int np = 0; np < 2; np++)
#pragma unroll
                for (int mt = 0; mt < 2; mt++)
#pragma unroll
                    for (int half = 0; half < 2; half++)
                        MMA16816(acc[mt][np * 2 + half], ah[mt],
                                 blf[np][half * 2], blf[np][half * 2 + 1]);
#pragma unroll
            for (int np = 0; np < 2; np++)
#pragma unroll
                for (int mt = 0; mt < 2; mt++)
#pragma unroll
                    for (int half = 0; half < 2; half++)
                        MMA16816(acc[mt][np * 2 + half], al[mt],
                                 bhf[np][half * 2], bhf[np][half * 2 + 1]);
        }
        __syncthreads();
    }

    int mrow = m0 + wm * 32 + (lane >> 2);
#pragma unroll
    for (int mt = 0; mt < 2; mt++) {
#pragma unroll
        for (int nt = 0; nt < 4; nt++) {
            int n = n0 + wn * 32 + nt * 8 + (lane & 3) * 2;
            float bx = bias[n], by = bias[n + 1];
            float2 v0 = make_float2(acc[mt][nt][0] + bx, acc[mt][nt][1] + by);
            float2 v1 = make_float2(acc[mt][nt][2] + bx, acc[mt][nt][3] + by);
            int m_a = mrow + mt * 16;
            int m_b = m_a + 8;
            if (MODE == 0) {
                int sec = n >> 10;
                int c2 = n & (Cc - 1);
                int h = c2 >> 6, d = c2 & 63;
                __nv_bfloat16 *dh, *dl;
                float scale;
                if (sec == 0)      { dh = g_Qhi; dl = g_Qlo; scale = 0.125f; }
                else if (sec == 1) { dh = g_Khi; dl = g_Klo; scale = 1.0f; }
                else               { dh = g_Vhi; dl = g_Vlo; scale = 1.0f; }
                v0.x *= scale; v0.y *= scale; v1.x *= scale; v1.y *= scale;
                int ba = m_a >> 11, ta = m_a & (Tt - 1);
                int bb2 = m_b >> 11, tb = m_b & (Tt - 1);
                size_t o0 = (((size_t)(ba * Hh + h)) * Tt + ta) * HD + d;
                size_t o1 = (((size_t)(bb2 * Hh + h)) * Tt + tb) * HD + d;
                __nv_bfloat162 hi = __floats2bfloat162_rn(v0.x, v0.y);
                __nv_bfloat162 lo = __floats2bfloat162_rn(
                    v0.x - __bfloat162float(hi.x), v0.y - __bfloat162float(hi.y));
                *(__nv_bfloat162*)&dh[o0] = hi;
                *(__nv_bfloat162*)&dl[o0] = lo;
                hi = __floats2bfloat162_rn(v1.x, v1.y);
                lo = __floats2bfloat162_rn(
                    v1.x - __bfloat162float(hi.x), v1.y - __bfloat162float(hi.y));
                *(__nv_bfloat162*)&dh[o1] = hi;
                *(__nv_bfloat162*)&dl[o1] = lo;
            } else {
                *(float2*)&out[(size_t)m_a * Cc + n] = v0;
                *(float2*)&out[(size_t)m_b * Cc + n] = v1;
            }
        }
    }
}

// ---------------------------------------------------------------------------
// Tensor-core flash attention, bf16 hi/lo split (3-term), Bq=64, Bk=64,
// 128 threads (4 warps x 16 q-rows).
// ---------------------------------------------------------------------------
#define APAD 72
#define AMAT (64*APAD)               // elems per smem matrix
#define ASMEM (6*AMAT*2)             // 55296 B

__global__ __launch_bounds__(128, 3) void attn_tc() {
    extern __shared__ __nv_bfloat16 sa[];
    __nv_bfloat16* Qh = sa;
    __nv_bfloat16* Ql = sa + AMAT;
    __nv_bfloat16* Kh = sa + 2 * AMAT;
    __nv_bfloat16* Kl = sa + 3 * AMAT;
    __nv_bfloat16* Vh = sa + 4 * AMAT;
    __nv_bfloat16* Vl = sa + 5 * AMAT;
    uint32_t sQh = smem_u32(Qh), sQl = smem_u32(Ql);
    uint32_t sKh = smem_u32(Kh), sKl = smem_u32(Kl);
    uint32_t sVh = smem_u32(Vh), sVl = smem_u32(Vl);

    int tid = threadIdx.x;
    int lane = tid & 31, w = tid >> 5;
    int bh = blockIdx.y;
    int qtile = (gridDim.x - 1) - blockIdx.x;    // heavy tiles first
    int q0 = qtile * 64;

    const __nv_bfloat16* gQh = g_Qhi + (size_t)bh * Tt * HD;
    const __nv_bfloat16* gQl = g_Qlo + (size_t)bh * Tt * HD;
    const __nv_bfloat16* gKh = g_Khi + (size_t)bh * Tt * HD;
    const __nv_bfloat16* gKl = g_Klo + (size_t)bh * Tt * HD;
    const __nv_bfloat16* gVh = g_Vthi + (size_t)bh * HD * Tt;
    const __nv_bfloat16* gVl = g_Vtlo + (size_t)bh * HD * Tt;

#pragma unroll
    for (int it = 0; it < 4; it++) {
        int idx = it * 128 + tid;
        int row = idx >> 3, seg = idx & 7;
        uint32_t so = (uint32_t)(row * APAD + seg * 8) * 2;
        size_t go = (size_t)(q0 + row) * HD + seg * 8;
        cp_async16(sQh + so, gQh + go);
        cp_async16(sQl + so, gQl + go);
    }
    cp_commit();

    float o[8][4] = {};
    float mrow[2] = {-1e30f, -1e30f};
    float lrow[2] = {0.0f, 0.0f};

    int r0 = lane >> 2;
    int qrow_loc = w * 16 + r0;

    for (int kt = 0; kt <= qtile; kt++) {
        int kv0 = kt * 64;
        __syncthreads();
#pragma unroll
        for (int it = 0; it < 4; it++) {
            int idx = it * 128 + tid;
            int row = idx >> 3, seg = idx & 7;
            uint32_t so = (uint32_t)(row * APAD + seg * 8) * 2;
            size_t gk = (size_t)(kv0 + row) * HD + seg * 8;
            size_t gv = (size_t)row * Tt + kv0 + seg * 8;
            cp_async16(sKh + so, gKh + gk);
            cp_async16(sKl + so, gKl + gk);
            cp_async16(sVh + so, gVh + gv);
            cp_async16(sVl + so, gVl + gv);
        }
        cp_commit();
        asm volatile("cp.async.wait_group 0;" ::: "memory");
        __syncthreads();

        // ---- S = Q K^T  (3-term split) ----
        float s[8][4] = {};
#pragma unroll
        for (int ks = 0; ks < 4; ks++) {
            uint32_t aqh[4], aql[4], bkh[4][4], bkl[4][4];
            uint32_t aaddr = (uint32_t)((w * 16 + (lane & 15)) * APAD + ks * 16 + (lane >> 4) * 8) * 2;
            LDSM_X4(aqh, sQh + aaddr);
            LDSM_X4(aql, sQl + aaddr);
#pragma unroll
            for (int ntp = 0; ntp < 4; ntp++) {
                uint32_t baddr = (uint32_t)((ntp * 16 + (lane >> 4) * 8 + (lane & 7)) * APAD +
                                            ks * 16 + ((lane >> 3) & 1) * 8) * 2;
                LDSM_X4(bkh[ntp], sKh + baddr);
                LDSM_X4(bkl[ntp], sKl + baddr);
            }
#pragma unroll
            for (int ntp = 0; ntp < 4; ntp++)
#pragma unroll
                for (int h2 = 0; h2 < 2; h2++)
                    MMA16816(s[ntp * 2 + h2], aqh, bkh[ntp][h2 * 2], bkh[ntp][h2 * 2 + 1]);
#pragma unroll
            for (int ntp = 0; ntp < 4; ntp++)
#pragma unroll
                for (int h2 = 0; h2 < 2; h2++)
                    MMA16816(s[ntp * 2 + h2], aqh, bkl[ntp][h2 * 2], bkl[ntp][h2 * 2 + 1]);
#pragma unroll
            for (int ntp = 0; ntp < 4; ntp++)
#pragma unroll
                for (int h2 = 0; h2 < 2; h2++)
                    MMA16816(s[ntp * 2 + h2], aql, bkh[ntp][h2 * 2], bkh[ntp][h2 * 2 + 1]);
        }

        if (kt == qtile) {
#pragma unroll
            for (int nt = 0; nt < 8; nt++) {
#pragma unroll
                for (int j = 0; j < 4; j++) {
                    int c = nt * 8 + (lane & 3) * 2 + (j & 1);
                    int r = qrow_loc + ((j >> 1) ? 8 : 0);
                    if (c > r) s[nt][j] = -1e30f;
                }
            }
        }

        // ---- online softmax ----
#pragma unroll
        for (int rr = 0; rr < 2; rr++) {
            float rm = -1e30f;
#pragma unroll
            for (int nt = 0; nt < 8; nt++)
                rm = fmaxf(rm, fmaxf(s[nt][rr * 2], s[nt][rr * 2 + 1]));
            rm = fmaxf(rm, __shfl_xor_sync(0xffffffffu, rm, 1));
            rm = fmaxf(rm, __shfl_xor_sync(0xffffffffu, rm, 2));
            float mnew = fmaxf(mrow[rr], rm);
            float alpha = __expf(mrow[rr] - mnew);
            mrow[rr] = mnew;
            float rs = 0.0f;
#pragma unroll
            for (int nt = 0; nt < 8; nt++) {
                s[nt][rr * 2]     = __expf(s[nt][rr * 2] - mnew);
                s[nt][rr * 2 + 1] = __expf(s[nt][rr * 2 + 1] - mnew);
                rs += s[nt][rr * 2] + s[nt][rr * 2 + 1];
            }
            rs += __shfl_xor_sync(0xffffffffu, rs, 1);
            rs += __shfl_xor_sync(0xffffffffu, rs, 2);
            lrow[rr] = lrow[rr] * alpha + rs;
#pragma unroll
            for (int dt = 0; dt < 8; dt++) {
                o[dt][rr * 2]     *= alpha;
                o[dt][rr * 2 + 1] *= alpha;
            }
        }

        // ---- O += P V ----
#pragma unroll
        for (int ksv = 0; ksv < 4; ksv++) {
            uint32_t pah[4], pal[4];
#pragma unroll
            for (int q = 0; q < 4; q++) {
                int nt = 2 * ksv + (q >> 1);
                int j0 = (q & 1) * 2;
                float x = s[nt][j0], y = s[nt][j0 + 1];
                __nv_bfloat162 hv = __floats2bfloat162_rn(x, y);
                __nv_bfloat162 lv = __floats2bfloat162_rn(
                    x - __bfloat162float(hv.x), y - __bfloat162float(hv.y));
                pah[q] = *(uint32_t*)&hv;
                pal[q] = *(uint32_t*)&lv;
            }
            uint32_t bvh[4][4], bvl[4][4];
#pragma unroll
            for (int dtp = 0; dtp < 4; dtp++) {
                uint32_t baddr = (uint32_t)((dtp * 16 + (lane >> 4) * 8 + (lane & 7)) * APAD +
                                            ksv * 16 + ((lane >> 3) & 1) * 8) * 2;
                LDSM_X4(bvh[dtp], sVh + baddr);
                LDSM_X4(bvl[dtp], sVl + baddr);
            }
#pragma unroll
            for (int dtp = 0; dtp < 4; dtp++)
#pragma unroll
                for (int h2 = 0; h2 < 2; h2++)
                    MMA16816(o[dtp * 2 + h2], pah, bvh[dtp][h2 * 2], bvh[dtp][h2 * 2 + 1]);
#pragma unroll
            for (int dtp = 0; dtp < 4; dtp++)
#pragma unroll
                for (int h2 = 0; h2 < 2; h2++)
                    MMA16816(o[dtp * 2 + h2], pah, bvl[dtp][h2 * 2], bvl[dtp][h2 * 2 + 1]);
#pragma unroll
            for (int dtp = 0; dtp < 4; dtp++)
#pragma unroll
                for (int h2 = 0; h2 < 2; h2++)
                    MMA16816(o[dtp * 2 + h2], pal, bvh[dtp][h2 * 2], bvh[dtp][h2 * 2 + 1]);
        }
    }

    // ---- epilogue: normalize, emit Y as bf16 hi/lo [B,T,C] ----
    float inv0 = 1.0f / lrow[0];
    float inv1 = 1.0f / lrow[1];
    int b = bh >> 4, h = bh & 15;
    int gq0 = q0 + w * 16 + r0;
    int gq1 = gq0 + 8;
#pragma unroll
    for (int dt = 0; dt < 8; dt++) {
        int col = h * HD + dt * 8 + (lane & 3) * 2;
        size_t o0 = (size_t)(b * Tt + gq0) * Cc + col;
        size_t o1 = (size_t)(b * Tt + gq1) * Cc + col;
        float y0 = o[dt][0] * inv0, y1 = o[dt][1] * inv0;
        float y2 = o[dt][2] * inv1, y3 = o[dt][3] * inv1;
        __nv_bfloat162 hv = __floats2bfloat162_rn(y0, y1);
        __nv_bfloat162 lv = __floats2bfloat162_rn(
            y0 - __bfloat162float(hv.x), y1 - __bfloat162float(hv.y));
        *(__nv_bfloat162*)&g_Yhi[o0] = hv;
        *(__nv_bfloat162*)&g_Ylo[o0] = lv;
        hv = __floats2bfloat162_rn(y2, y3);
        lv = __floats2bfloat162_rn(
            y2 - __bfloat162float(hv.x), y3 - __bfloat162float(hv.y));
        *(__nv_bfloat162*)&g_Yhi[o1] = hv;
        *(__nv_bfloat162*)&g_Ylo[o1] = lv;
    }
}

// ---------------------------------------------------------------------------
extern "C" void kernel_launch(void* const* d_in, const int* in_sizes, int n_in,
                              void* d_out, int out_size) {
    const float* x      = (const float*)d_in[0];
    const float* W_attn = (const float*)d_in[1];
    const float* b_attn = (const float*)d_in[2];
    const float* W_proj = (const float*)d_in[3];
    const float* b_proj = (const float*)d_in[4];
    float* out = (float*)d_out;

    __nv_bfloat16 *xhi, *xlo, *wahi, *walo, *wphi, *wplo, *yhi, *ylo;
    cudaGetSymbolAddress((void**)&xhi,  g_Xhi);
    cudaGetSymbolAddress((void**)&xlo,  g_Xlo);
    cudaGetSymbolAddress((void**)&wahi, g_WAhi);
    cudaGetSymbolAddress((void**)&walo, g_WAlo);
    cudaGetSymbolAddress((void**)&wphi, g_WPhi);
    cudaGetSymbolAddress((void**)&wplo, g_WPlo);
    cudaGetSymbolAddress((void**)&yhi,  g_Yhi);
    cudaGetSymbolAddress((void**)&ylo,  g_Ylo);

    cudaFuncSetAttribute(tc_gemm<0>, cudaFuncAttributeMaxDynamicSharedMemorySize, GSMEM);
    cudaFuncSetAttribute(tc_gemm<1>, cudaFuncAttributeMaxDynamicSharedMemorySize, GSMEM);
    cudaFuncSetAttribute(attn_tc, cudaFuncAttributeMaxDynamicSharedMemorySize, ASMEM);

    convert_x_kernel<<<1024, 256>>>((const float4*)x, MR * Cc / 4);
    transconv_kernel<<<dim3(3 * Cc / 32, Cc / 32), dim3(32, 8)>>>(W_attn, wahi, walo, Cc, 3 * Cc);
    transconv_kernel<<<dim3(Cc / 32, Cc / 32), dim3(32, 8)>>>(W_proj, wphi, wplo, Cc, Cc);

    tc_gemm<0><<<dim3(3 * Cc / 64, MR / 128), 256, GSMEM>>>(xhi, xlo, wahi, walo, b_attn, nullptr);

    vtrans_kernel<<<dim3(Tt / 32, HD / 32, Bb * Hh), dim3(32, 8)>>>();

    attn_tc<<<dim3(Tt / 64, Bb * Hh), 128, ASMEM>>>();

    tc_gemm<1><<<dim3(Cc / 64, MR / 128), 256, GSMEM>>>(yhi, ylo, wphi, wplo, b_proj, out);
}

// round 8
// speedup vs baseline: 1.2408x; 1.1405x over previous
#include <cuda_runtime.h>
#include <cuda_bf16.h>
#include <cstdint>

#define Bb 4
#define Tt 2048
#define Cc 1024
#define Hh 16
#define HD 64
#define MR (Bb*Tt)      // 8192 rows

// ---------------------------------------------------------------------------
// device scratch (allocation-free rule)
// ---------------------------------------------------------------------------
__device__ __nv_bfloat16 g_Qhi[Bb*Hh*Tt*HD];
__device__ __nv_bfloat16 g_Qlo[Bb*Hh*Tt*HD];
__device__ __nv_bfloat16 g_Khi[Bb*Hh*Tt*HD];
__device__ __nv_bfloat16 g_Klo[Bb*Hh*Tt*HD];
__device__ __nv_bfloat16 g_Vhi[Bb*Hh*Tt*HD];
__device__ __nv_bfloat16 g_Vlo[Bb*Hh*Tt*HD];
__device__ __nv_bfloat16 g_Vthi[Bb*Hh*Tt*HD];   // [bh][d][kv]
__device__ __nv_bfloat16 g_Vtlo[Bb*Hh*Tt*HD];
__device__ __nv_bfloat16 g_Xhi[MR*Cc];
__device__ __nv_bfloat16 g_Xlo[MR*Cc];
__device__ __nv_bfloat16 g_WAhi[3*Cc*Cc];
__device__ __nv_bfloat16 g_WAlo[3*Cc*Cc];
__device__ __nv_bfloat16 g_WPhi[Cc*Cc];
__device__ __nv_bfloat16 g_WPlo[Cc*Cc];
__device__ __nv_bfloat16 g_Yhi[MR*Cc];
__device__ __nv_bfloat16 g_Ylo[MR*Cc];

// ---------------------------------------------------------------------------
// helpers (base sm_10x-legal PTX only: cp.async / ldmatrix / mma.sync)
// ---------------------------------------------------------------------------
__device__ __forceinline__ uint32_t smem_u32(const void* p) {
    uint32_t a;
    asm("{ .reg .u64 t; cvta.to.shared.u64 t, %1; cvt.u32.u64 %0, t; }" : "=r"(a) : "l"(p));
    return a;
}

__device__ __forceinline__ void cp_async16(uint32_t s, const void* g) {
    asm volatile("cp.async.cg.shared.global [%0], [%1], 16;" :: "r"(s), "l"(g));
}
__device__ __forceinline__ void cp_commit() {
    asm volatile("cp.async.commit_group;" ::: "memory");
}

#define LDSM_X4(r, addr) \
    asm volatile("ldmatrix.sync.aligned.m8n8.x4.shared.b16 {%0,%1,%2,%3}, [%4];" \
        : "=r"((r)[0]), "=r"((r)[1]), "=r"((r)[2]), "=r"((r)[3]) : "r"(addr))

#define MMA16816(c, a, b0v, b1v) \
    asm volatile("mma.sync.aligned.m16n8k16.row.col.f32.bf16.bf16.f32 " \
        "{%0,%1,%2,%3}, {%4,%5,%6,%7}, {%8,%9}, {%0,%1,%2,%3};" \
        : "+f"((c)[0]), "+f"((c)[1]), "+f"((c)[2]), "+f"((c)[3]) \
        : "r"((a)[0]), "r"((a)[1]), "r"((a)[2]), "r"((a)[3]), "r"(b0v), "r"(b1v))

// ---------------------------------------------------------------------------
// prep kernels
// ---------------------------------------------------------------------------
__global__ void convert_x_kernel(const float4* __restrict__ x, int n4) {
    __nv_bfloat162* hi2 = (__nv_bfloat162*)g_Xhi;
    __nv_bfloat162* lo2 = (__nv_bfloat162*)g_Xlo;
    for (int i = blockIdx.x * blockDim.x + threadIdx.x; i < n4; i += gridDim.x * blockDim.x) {
        float4 v = x[i];
        __nv_bfloat16 h0 = __float2bfloat16(v.x), h1 = __float2bfloat16(v.y);
        __nv_bfloat16 h2 = __float2bfloat16(v.z), h3 = __float2bfloat16(v.w);
        __nv_bfloat162 a, b, c, d;
        a.x = h0; a.y = h1; b.x = h2; b.y = h3;
        c.x = __float2bfloat16(v.x - __bfloat162float(h0));
        c.y = __float2bfloat16(v.y - __bfloat162float(h1));
        d.x = __float2bfloat16(v.z - __bfloat162float(h2));
        d.y = __float2bfloat16(v.w - __bfloat162float(h3));
        hi2[i * 2] = a; hi2[i * 2 + 1] = b;
        lo2[i * 2] = c; lo2[i * 2 + 1] = d;
    }
}

// src [K,N] fp32 -> dst [N,K] bf16 hi/lo
__global__ void transconv_kernel(const float* __restrict__ src, __nv_bfloat16* __restrict__ dhi,
                                 __nv_bfloat16* __restrict__ dlo, int K, int N) {
    __shared__ float sm[32][33];
    int n0 = blockIdx.x * 32, k0 = blockIdx.y * 32;
    int tx = threadIdx.x, ty = threadIdx.y;   // 32 x 8
#pragma unroll
    for (int i = 0; i < 32; i += 8)
        sm[ty + i][tx] = src[(size_t)(k0 + ty + i) * N + n0 + tx];
    __syncthreads();
#pragma unroll
    for (int i = 0; i < 32; i += 8) {
        float v = sm[tx][ty + i];
        __nv_bfloat16 h = __float2bfloat16(v);
        size_t o = (size_t)(n0 + ty + i) * K + k0 + tx;
        dhi[o] = h;
        dlo[o] = __float2bfloat16(v - __bfloat162float(h));
    }
}

// V [bh][kv][d] bf16 -> Vt [bh][d][kv] bf16 (hi and lo)
__global__ void vtrans_kernel() {
    __shared__ __nv_bfloat16 th[32][33], tl[32][33];
    int kv0 = blockIdx.x * 32, d0 = blockIdx.y * 32, bh = blockIdx.z;
    int tx = threadIdx.x, ty = threadIdx.y;   // 32 x 8
    const __nv_bfloat16* sh = g_Vhi + (size_t)bh * Tt * HD;
    const __nv_bfloat16* sl = g_Vlo + (size_t)bh * Tt * HD;
    __nv_bfloat16* dh = g_Vthi + (size_t)bh * HD * Tt;
    __nv_bfloat16* dl = g_Vtlo + (size_t)bh * HD * Tt;
#pragma unroll
    for (int i = 0; i < 32; i += 8) {
        th[ty + i][tx] = sh[(size_t)(kv0 + ty + i) * HD + d0 + tx];
        tl[ty + i][tx] = sl[(size_t)(kv0 + ty + i) * HD + d0 + tx];
    }
    __syncthreads();
#pragma unroll
    for (int i = 0; i < 32; i += 8) {
        dh[(size_t)(d0 + ty + i) * Tt + kv0 + tx] = th[tx][ty + i];
        dl[(size_t)(d0 + ty + i) * Tt + kv0 + tx] = tl[tx][ty + i];
    }
}

// ---------------------------------------------------------------------------
// HMMA bf16 (hi/lo split) GEMM: CTA tile 128x128, 4 warps of 64x64, BK=32,
// cp.async double-buffered, 2 CTAs/SM. 16.4 MACs per smem byte (was 8.4).
// MODE 0: emit Q(0.125x)/K/V as bf16 hi/lo into [bh][t][d] arrays.
// MODE 1: row-major fp32 out [MR,Cc].
// ---------------------------------------------------------------------------
#define BK 32
#define PAD 40
#define AMATB (128*PAD*2)            // 10240 (A hi or lo)
#define BMATB (128*PAD*2)            // 10240 (B hi or lo)
#define B_OFF (2*AMATB)              // 20480
#define BUFB (2*AMATB + 2*BMATB)     // 40960
#define GSMEM (2*BUFB)               // 81920

__device__ __forceinline__ void issue_chunk(
    uint32_t sbase,
    const __nv_bfloat16* __restrict__ Ahi, const __nv_bfloat16* __restrict__ Alo,
    const __nv_bfloat16* __restrict__ Bhi, const __nv_bfloat16* __restrict__ Blo,
    int m0, int n0, int kc, int tid)
{
    // A: 128 rows x 32 cols (4 segs of 8), hi+lo ; B: same shape
#pragma unroll
    for (int it = 0; it < 4; it++) {
        int idx = it * 128 + tid;            // 0..511
        int row = idx >> 2, seg = idx & 3;
        uint32_t soff = (uint32_t)(row * PAD + seg * 8) * 2;
        size_t ga = (size_t)(m0 + row) * Cc + kc + seg * 8;
        size_t gb = (size_t)(n0 + row) * Cc + kc + seg * 8;
        cp_async16(sbase + soff,                 Ahi + ga);
        cp_async16(sbase + AMATB + soff,         Alo + ga);
        cp_async16(sbase + B_OFF + soff,         Bhi + gb);
        cp_async16(sbase + B_OFF + BMATB + soff, Blo + gb);
    }
    cp_commit();
}

template <int MODE>
__global__ __launch_bounds__(128, 2)
void tc_gemm(const __nv_bfloat16* __restrict__ Ahi, const __nv_bfloat16* __restrict__ Alo,
             const __nv_bfloat16* __restrict__ Bhi, const __nv_bfloat16* __restrict__ Blo,
             const float* __restrict__ bias, float* __restrict__ out) {
    extern __shared__ char smx[];
    uint32_t sb = smem_u32(smx);
    int tid = threadIdx.x;
    int lane = tid & 31, warp = tid >> 5;
    int wm = warp >> 1;         // 2 m-warps (64 rows each)
    int wn = warp & 1;          // 2 n-warps (64 cols each)
    int m0 = blockIdx.y * 128, n0 = blockIdx.x * 128;

    float acc[4][8][4] = {};    // [mt][nt][frag]  (64x64 per warp)

    issue_chunk(sb, Ahi, Alo, Bhi, Blo, m0, n0, 0, tid);

    const int NCH = Cc / BK;   // 32
    int arow = wm * 64 + (lane & 15);
    int acol_base = (lane >> 4) * 8;
    int brow = wn * 64 + (lane >> 4) * 8 + (lane & 7);
    int bcol_base = ((lane >> 3) & 1) * 8;

    for (int i = 0; i < NCH; i++) {
        if (i + 1 < NCH) {
            issue_chunk(sb + ((i + 1) & 1) * BUFB, Ahi, Alo, Bhi, Blo, m0, n0, (i + 1) * BK, tid);
            asm volatile("cp.async.wait_group 1;" ::: "memory");
        } else {
            asm volatile("cp.async.wait_group 0;" ::: "memory");
        }
        __syncthreads();
        uint32_t buf = sb + (i & 1) * BUFB;

#pragma unroll
        for (int ks = 0; ks < 2; ks++) {
            uint32_t ah[4][4], al[4][4], bhf[4][4], blf[4][4];
            int acol = ks * 16 + acol_base;
#pragma unroll
            for (int mt = 0; mt < 4; mt++) {
                uint32_t addr = buf + (uint32_t)((arow + mt * 16) * PAD + acol) * 2;
                LDSM_X4(ah[mt], addr);
                LDSM_X4(al[mt], addr + AMATB);
            }
            int bcol = ks * 16 + bcol_base;
#pragma unroll
            for (int np = 0; np < 4; np++) {
                uint32_t addr = buf + B_OFF +
                                (uint32_t)((brow + np * 16) * PAD + bcol) * 2;
                LDSM_X4(bhf[np], addr);
                LDSM_X4(blf[np], addr + BMATB);
            }
            // three term passes, 32 independent MMAs each
#pragma unroll
            for (int np = 0; np < 4; np++)
#pragma unroll
                for (int mt = 0; mt < 4; mt++)
#pragma unroll
                    for (int half = 0; half < 2; half++)
                        MMA16816(acc[mt][np * 2 + half], ah[mt],
                                 bhf[np][half * 2], bhf[np][half * 2 + 1]);
#pragma unroll
            for (int np = 0; np < 4; np++)
#pragma unroll
                for (int mt = 0; mt < 4; mt++)
#pragma unroll
                    for (int half = 0; half < 2; half++)
                        MMA16816(acc[mt][np * 2 + half], ah[mt],
                                 blf[np][half * 2], blf[np][half * 2 + 1]);
#pragma unroll
            for (int np = 0; np < 4; np++)
#pragma unroll
                for (int mt = 0; mt < 4; mt++)
#pragma unroll
                    for (int half = 0; half < 2; half++)
                        MMA16816(acc[mt][np * 2 + half], al[mt],
                                 bhf[np][half * 2], bhf[np][half * 2 + 1]);
        }
        __syncthreads();
    }

    int mrow = m0 + wm * 64 + (lane >> 2);
#pragma unroll
    for (int mt = 0; mt < 4; mt++) {
#pragma unroll
        for (int nt = 0; nt < 8; nt++) {
            int n = n0 + wn * 64 + nt * 8 + (lane & 3) * 2;
            float bx = bias[n], by = bias[n + 1];
            float2 v0 = make_float2(acc[mt][nt][0] + bx, acc[mt][nt][1] + by);
            float2 v1 = make_float2(acc[mt][nt][2] + bx, acc[mt][nt][3] + by);
            int m_a = mrow + mt * 16;
            int m_b = m_a + 8;
            if (MODE == 0) {
                int sec = n >> 10;
                int c2 = n & (Cc - 1);
                int h = c2 >> 6, d = c2 & 63;
                __nv_bfloat16 *dh, *dl;
                float scale;
                if (sec == 0)      { dh = g_Qhi; dl = g_Qlo; scale = 0.125f; }
                else if (sec == 1) { dh = g_Khi; dl = g_Klo; scale = 1.0f; }
                else               { dh = g_Vhi; dl = g_Vlo; scale = 1.0f; }
                v0.x *= scale; v0.y *= scale; v1.x *= scale; v1.y *= scale;
                int ba = m_a >> 11, ta = m_a & (Tt - 1);
                int bb2 = m_b >> 11, tb = m_b & (Tt - 1);
                size_t o0 = (((size_t)(ba * Hh + h)) * Tt + ta) * HD + d;
                size_t o1 = (((size_t)(bb2 * Hh + h)) * Tt + tb) * HD + d;
                __nv_bfloat162 hi = __floats2bfloat162_rn(v0.x, v0.y);
                __nv_bfloat162 lo = __floats2bfloat162_rn(
                    v0.x - __bfloat162float(hi.x), v0.y - __bfloat162float(hi.y));
                *(__nv_bfloat162*)&dh[o0] = hi;
                *(__nv_bfloat162*)&dl[o0] = lo;
                hi = __floats2bfloat162_rn(v1.x, v1.y);
                lo = __floats2bfloat162_rn(
                    v1.x - __bfloat162float(hi.x), v1.y - __bfloat162float(hi.y));
                *(__nv_bfloat162*)&dh[o1] = hi;
                *(__nv_bfloat162*)&dl[o1] = lo;
            } else {
                *(float2*)&out[(size_t)m_a * Cc + n] = v0;
                *(float2*)&out[(size_t)m_b * Cc + n] = v1;
            }
        }
    }
}

// ---------------------------------------------------------------------------
// Tensor-core flash attention, bf16 hi/lo split (3-term), Bq=64, Bk=64,
// 128 threads (4 warps x 16 q-rows).
// ---------------------------------------------------------------------------
#define APAD 72
#define AMAT (64*APAD)               // elems per smem matrix
#define ASMEM (6*AMAT*2)             // 55296 B

__global__ __launch_bounds__(128, 3) void attn_tc() {
    extern __shared__ __nv_bfloat16 sa[];
    __nv_bfloat16* Qh = sa;
    __nv_bfloat16* Ql = sa + AMAT;
    __nv_bfloat16* Kh = sa + 2 * AMAT;
    __nv_bfloat16* Kl = sa + 3 * AMAT;
    __nv_bfloat16* Vh = sa + 4 * AMAT;
    __nv_bfloat16* Vl = sa + 5 * AMAT;
    uint32_t sQh = smem_u32(Qh), sQl = smem_u32(Ql);
    uint32_t sKh = smem_u32(Kh), sKl = smem_u32(Kl);
    uint32_t sVh = smem_u32(Vh), sVl = smem_u32(Vl);

    int tid = threadIdx.x;
    int lane = tid & 31, w = tid >> 5;
    int bh = blockIdx.y;
    int qtile = (gridDim.x - 1) - blockIdx.x;    // heavy tiles first
    int q0 = qtile * 64;

    const __nv_bfloat16* gQh = g_Qhi + (size_t)bh * Tt * HD;
    const __nv_bfloat16* gQl = g_Qlo + (size_t)bh * Tt * HD;
    const __nv_bfloat16* gKh = g_Khi + (size_t)bh * Tt * HD;
    const __nv_bfloat16* gKl = g_Klo + (size_t)bh * Tt * HD;
    const __nv_bfloat16* gVh = g_Vthi + (size_t)bh * HD * Tt;
    const __nv_bfloat16* gVl = g_Vtlo + (size_t)bh * HD * Tt;

#pragma unroll
    for (int it = 0; it < 4; it++) {
        int idx = it * 128 + tid;
        int row = idx >> 3, seg = idx & 7;
        uint32_t so = (uint32_t)(row * APAD + seg * 8) * 2;
        size_t go = (size_t)(q0 + row) * HD + seg * 8;
        cp_async16(sQh + so, gQh + go);
        cp_async16(sQl + so, gQl + go);
    }
    cp_commit();

    float o[8][4] = {};
    float mrow[2] = {-1e30f, -1e30f};
    float lrow[2] = {0.0f, 0.0f};

    int r0 = lane >> 2;
    int qrow_loc = w * 16 + r0;

    for (int kt = 0; kt <= qtile; kt++) {
        int kv0 = kt * 64;
        __syncthreads();
#pragma unroll
        for (int it = 0; it < 4; it++) {
            int idx = it * 128 + tid;
            int row = idx >> 3, seg = idx & 7;
            uint32_t so = (uint32_t)(row * APAD + seg * 8) * 2;
            size_t gk = (size_t)(kv0 + row) * HD + seg * 8;
            size_t gv = (size_t)row * Tt + kv0 + seg * 8;
            cp_async16(sKh + so, gKh + gk);
            cp_async16(sKl + so, gKl + gk);
            cp_async16(sVh + so, gVh + gv);
            cp_async16(sVl + so, gVl + gv);
        }
        cp_commit();
        asm volatile("cp.async.wait_group 0;" ::: "memory");
        __syncthreads();

        // ---- S = Q K^T  (3-term split) ----
        float s[8][4] = {};
#pragma unroll
        for (int ks = 0; ks < 4; ks++) {
            uint32_t aqh[4], aql[4], bkh[4][4], bkl[4][4];
            uint32_t aaddr = (uint32_t)((w * 16 + (lane & 15)) * APAD + ks * 16 + (lane >> 4) * 8) * 2;
            LDSM_X4(aqh, sQh + aaddr);
            LDSM_X4(aql, sQl + aaddr);
#pragma unroll
            for (int ntp = 0; ntp < 4; ntp++) {
                uint32_t baddr = (uint32_t)((ntp * 16 + (lane >> 4) * 8 + (lane & 7)) * APAD +
                                            ks * 16 + ((lane >> 3) & 1) * 8) * 2;
                LDSM_X4(bkh[ntp], sKh + baddr);
                LDSM_X4(bkl[ntp], sKl + baddr);
            }
#pragma unroll
            for (int ntp = 0; ntp < 4; ntp++)
#pragma unroll
                for (int h2 = 0; h2 < 2; h2++)
                    MMA16816(s[ntp * 2 + h2], aqh, bkh[ntp][h2 * 2], bkh[ntp][h2 * 2 + 1]);
#pragma unroll
            for (int ntp = 0; ntp < 4; ntp++)
#pragma unroll
                for (int h2 = 0; h2 < 2; h2++)
                    MMA16816(s[ntp * 2 + h2], aqh, bkl[ntp][h2 * 2], bkl[ntp][h2 * 2 + 1]);
#pragma unroll
            for (int ntp = 0; ntp < 4; ntp++)
#pragma unroll
                for (int h2 = 0; h2 < 2; h2++)
                    MMA16816(s[ntp * 2 + h2], aql, bkh[ntp][h2 * 2], bkh[ntp][h2 * 2 + 1]);
        }

        if (kt == qtile) {
#pragma unroll
            for (int nt = 0; nt < 8; nt++) {
#pragma unroll
                for (int j = 0; j < 4; j++) {
                    int c = nt * 8 + (lane & 3) * 2 + (j & 1);
                    int r = qrow_loc + ((j >> 1) ? 8 : 0);
                    if (c > r) s[nt][j] = -1e30f;
                }
            }
        }

        // ---- online softmax ----
#pragma unroll
        for (int rr = 0; rr < 2; rr++) {
            float rm = -1e30f;
#pragma unroll
            for (int nt = 0; nt < 8; nt++)
                rm = fmaxf(rm, fmaxf(s[nt][rr * 2], s[nt][rr * 2 + 1]));
            rm = fmaxf(rm, __shfl_xor_sync(0xffffffffu, rm, 1));
            rm = fmaxf(rm, __shfl_xor_sync(0xffffffffu, rm, 2));
            float mnew = fmaxf(mrow[rr], rm);
            float alpha = __expf(mrow[rr] - mnew);
            mrow[rr] = mnew;
            float rs = 0.0f;
#pragma unroll
            for (int nt = 0; nt < 8; nt++) {
                s[nt][rr * 2]     = __expf(s[nt][rr * 2] - mnew);
                s[nt][rr * 2 + 1] = __expf(s[nt][rr * 2 + 1] - mnew);
                rs += s[nt][rr * 2] + s[nt][rr * 2 + 1];
            }
            rs += __shfl_xor_sync(0xffffffffu, rs, 1);
            rs += __shfl_xor_sync(0xffffffffu, rs, 2);
            lrow[rr] = lrow[rr] * alpha + rs;
#pragma unroll
            for (int dt = 0; dt < 8; dt++) {
                o[dt][rr * 2]     *= alpha;
                o[dt][rr * 2 + 1] *= alpha;
            }
        }

        // ---- O += P V ----
#pragma unroll
        for (int ksv = 0; ksv < 4; ksv++) {
            uint32_t pah[4], pal[4];
#pragma unroll
            for (int q = 0; q < 4; q++) {
                int nt = 2 * ksv + (q >> 1);
                int j0 = (q & 1) * 2;
                float x = s[nt][j0], y = s[nt][j0 + 1];
                __nv_bfloat162 hv = __floats2bfloat162_rn(x, y);
                __nv_bfloat162 lv = __floats2bfloat162_rn(
                    x - __bfloat162float(hv.x), y - __bfloat162float(hv.y));
                pah[q] = *(uint32_t*)&hv;
                pal[q] = *(uint32_t*)&lv;
            }
            uint32_t bvh[4][4], bvl[4][4];
#pragma unroll
            for (int dtp = 0; dtp < 4; dtp++) {
                uint32_t baddr = (uint32_t)((dtp * 16 + (lane >> 4) * 8 + (lane & 7)) * APAD +
                                            ksv * 16 + ((lane >> 3) & 1) * 8) * 2;
                LDSM_X4(bvh[dtp], sVh + baddr);
                LDSM_X4(bvl[dtp], sVl + baddr);
            }
#pragma unroll
            for (int dtp = 0; dtp < 4; dtp++)
#pragma unroll
                for (int h2 = 0; h2 < 2; h2++)
                    MMA16816(o[dtp * 2 + h2], pah, bvh[dtp][h2 * 2], bvh[dtp][h2 * 2 + 1]);
#pragma unroll
            for (int dtp = 0; dtp < 4; dtp++)
#pragma unroll
                for (int h2 = 0; h2 < 2; h2++)
                    MMA16816(o[dtp * 2 + h2], pah, bvl[dtp][h2 * 2], bvl[dtp][h2 * 2 + 1]);
#pragma unroll
            for (int dtp = 0; dtp < 4; dtp++)
#pragma unroll
                for (int h2 = 0; h2 < 2; h2++)
                    MMA16816(o[dtp * 2 + h2], pal, bvh[dtp][h2 * 2], bvh[dtp][h2 * 2 + 1]);
        }
    }

    // ---- epilogue: normalize, emit Y as bf16 hi/lo [B,T,C] ----
    float inv0 = 1.0f / lrow[0];
    float inv1 = 1.0f / lrow[1];
    int b = bh >> 4, h = bh & 15;
    int gq0 = q0 + w * 16 + r0;
    int gq1 = gq0 + 8;
#pragma unroll
    for (int dt = 0; dt < 8; dt++) {
        int col = h * HD + dt * 8 + (lane & 3) * 2;
        size_t o0 = (size_t)(b * Tt + gq0) * Cc + col;
        size_t o1 = (size_t)(b * Tt + gq1) * Cc + col;
        float y0 = o[dt][0] * inv0, y1 = o[dt][1] * inv0;
        float y2 = o[dt][2] * inv1, y3 = o[dt][3] * inv1;
        __nv_bfloat162 hv = __floats2bfloat162_rn(y0, y1);
        __nv_bfloat162 lv = __floats2bfloat162_rn(
            y0 - __bfloat162float(hv.x), y1 - __bfloat162float(hv.y));
        *(__nv_bfloat162*)&g_Yhi[o0] = hv;
        *(__nv_bfloat162*)&g_Ylo[o0] = lv;
        hv = __floats2bfloat162_rn(y2, y3);
        lv = __floats2bfloat162_rn(
            y2 - __bfloat162float(hv.x), y3 - __bfloat162float(hv.y));
        *(__nv_bfloat162*)&g_Yhi[o1] = hv;
        *(__nv_bfloat162*)&g_Ylo[o1] = lv;
    }
}

// ---------------------------------------------------------------------------
extern "C" void kernel_launch(void* const* d_in, const int* in_sizes, int n_in,
                              void* d_out, int out_size) {
    const float* x      = (const float*)d_in[0];
    const float* W_attn = (const float*)d_in[1];
    const float* b_attn = (const float*)d_in[2];
    const float* W_proj = (const float*)d_in[3];
    const float* b_proj = (const float*)d_in[4];
    float* out = (float*)d_out;

    __nv_bfloat16 *xhi, *xlo, *wahi, *walo, *wphi, *wplo, *yhi, *ylo;
    cudaGetSymbolAddress((void**)&xhi,  g_Xhi);
    cudaGetSymbolAddress((void**)&xlo,  g_Xlo);
    cudaGetSymbolAddress((void**)&wahi, g_WAhi);
    cudaGetSymbolAddress((void**)&walo, g_WAlo);
    cudaGetSymbolAddress((void**)&wphi, g_WPhi);
    cudaGetSymbolAddress((void**)&wplo, g_WPlo);
    cudaGetSymbolAddress((void**)&yhi,  g_Yhi);
    cudaGetSymbolAddress((void**)&ylo,  g_Ylo);

    cudaFuncSetAttribute(tc_gemm<0>, cudaFuncAttributeMaxDynamicSharedMemorySize, GSMEM);
    cudaFuncSetAttribute(tc_gemm<1>, cudaFuncAttributeMaxDynamicSharedMemorySize, GSMEM);
    cudaFuncSetAttribute(attn_tc, cudaFuncAttributeMaxDynamicSharedMemorySize, ASMEM);

    convert_x_kernel<<<1024, 256>>>((const float4*)x, MR * Cc / 4);
    transconv_kernel<<<dim3(3 * Cc / 32, Cc / 32), dim3(32, 8)>>>(W_attn, wahi, walo, Cc, 3 * Cc);
    transconv_kernel<<<dim3(Cc / 32, Cc / 32), dim3(32, 8)>>>(W_proj, wphi, wplo, Cc, Cc);

    tc_gemm<0><<<dim3(3 * Cc / 128, MR / 128), 128, GSMEM>>>(xhi, xlo, wahi, walo, b_attn, nullptr);

    vtrans_kernel<<<dim3(Tt / 32, HD / 32, Bb * Hh), dim3(32, 8)>>>();

    attn_tc<<<dim3(Tt / 64, Bb * Hh), 128, ASMEM>>>();

    tc_gemm<1><<<dim3(Cc / 128, MR / 128), 128, GSMEM>>>(yhi, ylo, wphi, wplo, b_proj, out);
}